// round 8
// baseline (speedup 1.0000x reference)
#include <cuda_runtime.h>

#define NC 24
#define LH 256
#define LW 256
#define PLANE (LH*LW)
#define R 8
#define EPSF 1e-4f

// per-plane block counts and layout inside the fused grid
#define NB_H 64              // hbox blocks per plane (4 rows each)
#define NB_V 16              // vbox blocks per plane (16 rows each)
#define NB_A 256             // apply blocks per plane (1 LR row -> 4 HR rows)
#define NB_PL (NB_H + NB_V + NB_A)   // 336

// scratch (allocation-free rule: __device__ globals)
__device__ float4 g_h4[NC*PLANE];   // {hsumI, hsumP, hsumIP, hsumII}
__device__ float2 g_AB[NC*PLANE];   // {A, B}
__device__ int    g_cnt_h[NC];
__device__ int    g_cnt_v[NC];

__global__ void k_reset()
{
    const int t = threadIdx.x;
    if (t < NC) { g_cnt_h[t] = 0; g_cnt_v[t] = 0; }
}

__device__ __forceinline__ float4 ldz(const float* __restrict__ row, int col)
{
    if (col < 0 || col >= LW) return make_float4(0.f, 0.f, 0.f, 0.f);
    return *reinterpret_cast<const float4*>(row + col);
}

// ---------------------------------------------------------------------------
// Fused pipeline kernel. Block roles by (blockIdx.x % NB_PL):
//   [0,64)    hbox   : horizontal 17-tap window sums (zero-padded), 4 rows/block
//   [64,80)   vbox   : vertical truncated sliding window + A,B solve, 16 rows/block
//   [80,336)  apply  : x4 bilinear upsample + out = A*I_hr + B, 4 HR rows/block
// Plane-major ordering => every block's dependencies have smaller blockIdx.
// ---------------------------------------------------------------------------
__global__ void k_fused(const float* __restrict__ p, const float* __restrict__ I,
                        const float* __restrict__ Ihr, float* __restrict__ out)
{
    __shared__ float2 sAB[3][LW];

    const int b   = blockIdx.x;
    const int pl  = b / NB_PL;
    const int r   = b - pl*NB_PL;
    const int tid = threadIdx.x;

    if (r < NB_H) {
        // ----------------------------- hbox -------------------------------
        const int rr  = tid >> 6;            // row in block 0..3
        const int tx  = tid & 63;
        const int row = r*4 + rr;
        const int gbase = pl*PLANE + row*LW;
        const int xb  = tx << 2;

        const float* __restrict__ Irow = I + gbase;
        const float* __restrict__ Prow = p + gbase;

        float4 i4[5], p4[5];
        #pragma unroll
        for (int j = 0; j < 5; j++) {
            const int col = xb - 8 + 4*j;
            i4[j] = ldz(Irow, col);
            p4[j] = ldz(Prow, col);
        }

        float iv[20], pv[20];
        #pragma unroll
        for (int j = 0; j < 5; j++) {
            iv[4*j+0] = i4[j].x; iv[4*j+1] = i4[j].y; iv[4*j+2] = i4[j].z; iv[4*j+3] = i4[j].w;
            pv[4*j+0] = p4[j].x; pv[4*j+1] = p4[j].y; pv[4*j+2] = p4[j].z; pv[4*j+3] = p4[j].w;
        }

        float sI = 0.f, sP = 0.f, sIP = 0.f, sII = 0.f;
        #pragma unroll
        for (int j = 0; j < 17; j++) {
            sI += iv[j]; sP += pv[j]; sIP += iv[j]*pv[j]; sII += iv[j]*iv[j];
        }

        float4* __restrict__ dst = g_h4 + gbase + xb;
        dst[0] = make_float4(sI, sP, sIP, sII);
        #pragma unroll
        for (int k = 1; k < 4; k++) {
            sI  += iv[16+k] - iv[k-1];
            sP  += pv[16+k] - pv[k-1];
            sIP += iv[16+k]*pv[16+k] - iv[k-1]*pv[k-1];
            sII += iv[16+k]*iv[16+k] - iv[k-1]*iv[k-1];
            dst[k] = make_float4(sI, sP, sIP, sII);
        }

        __threadfence();
        __syncthreads();
        if (tid == 0) atomicAdd(&g_cnt_h[pl], 1);

    } else if (r < NB_H + NB_V) {
        // ----------------------------- vbox -------------------------------
        if (tid == 0) {
            while (atomicAdd(&g_cnt_h[pl], 0) < NB_H) __nanosleep(64);
        }
        __syncthreads();
        __threadfence();

        const int c  = tid;                  // column
        const int y0 = (r - NB_H) * 16;

        const float4* __restrict__ h = g_h4 + pl*PLANE + c;

        float sI = 0.f, sP = 0.f, sIP = 0.f, sII = 0.f;
        {
            const int lo = max(y0 - R, 0);
            const int hi = y0 + R;           // y0 <= 240 -> hi <= 248 always
            for (int yy = lo; yy <= hi; yy++) {
                const float4 v = h[yy*LW];
                sI += v.x; sP += v.y; sIP += v.z; sII += v.w;
            }
        }

        const float cx = (float)(min(c + R, LW-1) - max(c - R, 0) + 1);
        float2* __restrict__ ABp = g_AB + pl*PLANE + c;

        for (int yo = y0; yo < y0 + 16; yo++) {
            const float cy  = (float)(min(yo + R, LH-1) - max(yo - R, 0) + 1);
            const float inv = 1.0f / (cx * cy);

            const float mI = sI*inv;
            const float mP = sP*inv;
            const float A  = (sIP*inv - mI*mP) / ((sII*inv - mI*mI) + EPSF);
            const float B  = mP - A*mI;

            ABp[yo*LW] = make_float2(A, B);

            const int ya = yo + R + 1;
            if (ya <= LH - 1) {
                const float4 v = h[ya*LW];
                sI += v.x; sP += v.y; sIP += v.z; sII += v.w;
            }
            const int ysub = yo - R;
            if (ysub >= 0) {
                const float4 v = h[ysub*LW];
                sI -= v.x; sP -= v.y; sIP -= v.z; sII -= v.w;
            }
        }

        __threadfence();
        __syncthreads();
        if (tid == 0) atomicAdd(&g_cnt_v[pl], 1);

    } else {
        // ----------------------------- apply ------------------------------
        if (tid == 0) {
            while (atomicAdd(&g_cnt_v[pl], 0) < NB_V) __nanosleep(64);
        }
        __syncthreads();
        __threadfence();

        const int k = r - (NB_H + NB_V);     // LR row 0..255
        const int t = tid;

        const int km = max(k - 1, 0);
        const int kp = min(k + 1, LH - 1);

        const float2* __restrict__ AB = g_AB + pl*PLANE;
        sAB[0][t] = AB[km*LW + t];
        sAB[1][t] = AB[k *LW + t];
        sAB[2][t] = AB[kp*LW + t];
        __syncthreads();

        const int xm = max(t - 1, 0);
        const int xp = min(t + 1, LW - 1);

        float xA[3][4], xB[3][4];
        #pragma unroll
        for (int j = 0; j < 3; j++) {
            const float2 vm = sAB[j][xm], v0 = sAB[j][t], vp = sAB[j][xp];
            xA[j][0] = 0.375f*vm.x + 0.625f*v0.x;  xB[j][0] = 0.375f*vm.y + 0.625f*v0.y;
            xA[j][1] = 0.125f*vm.x + 0.875f*v0.x;  xB[j][1] = 0.125f*vm.y + 0.875f*v0.y;
            xA[j][2] = 0.875f*v0.x + 0.125f*vp.x;  xB[j][2] = 0.875f*v0.y + 0.125f*vp.y;
            xA[j][3] = 0.625f*v0.x + 0.375f*vp.x;  xB[j][3] = 0.625f*v0.y + 0.375f*vp.y;
        }

        const int base = ((pl << 10) + (k << 2)) * 1024 + (t << 2);
        const float4 iv0 = __ldcs(reinterpret_cast<const float4*>(Ihr + base));
        const float4 iv1 = __ldcs(reinterpret_cast<const float4*>(Ihr + base + 1024));
        const float4 iv2 = __ldcs(reinterpret_cast<const float4*>(Ihr + base + 2048));
        const float4 iv3 = __ldcs(reinterpret_cast<const float4*>(Ihr + base + 3072));

        // y-weights: HR 4k+0: rows(k-1,k) w=(.375,.625); 4k+1: (.125,.875)
        //            4k+2: rows(k,k+1) w=(.875,.125);    4k+3: (.625,.375)
#define OUTV(IV, W0, J0, W1, J1)                                                \
    make_float4(                                                                \
        (W0*xA[J0][0] + W1*xA[J1][0])*IV.x + (W0*xB[J0][0] + W1*xB[J1][0]),     \
        (W0*xA[J0][1] + W1*xA[J1][1])*IV.y + (W0*xB[J0][1] + W1*xB[J1][1]),     \
        (W0*xA[J0][2] + W1*xA[J1][2])*IV.z + (W0*xB[J0][2] + W1*xB[J1][2]),     \
        (W0*xA[J0][3] + W1*xA[J1][3])*IV.w + (W0*xB[J0][3] + W1*xB[J1][3]))

        __stcs(reinterpret_cast<float4*>(out + base),        OUTV(iv0, 0.375f, 0, 0.625f, 1));
        __stcs(reinterpret_cast<float4*>(out + base + 1024), OUTV(iv1, 0.125f, 0, 0.875f, 1));
        __stcs(reinterpret_cast<float4*>(out + base + 2048), OUTV(iv2, 0.875f, 1, 0.125f, 2));
        __stcs(reinterpret_cast<float4*>(out + base + 3072), OUTV(iv3, 0.625f, 1, 0.375f, 2));
#undef OUTV
    }
}

// ---------------------------------------------------------------------------
extern "C" void kernel_launch(void* const* d_in, const int* in_sizes, int n_in,
                              void* d_out, int out_size)
{
    const float* p_lr = (const float*)d_in[0];
    const float* I_lr = (const float*)d_in[1];
    const float* I_hr = (const float*)d_in[2];
    float* out = (float*)d_out;

    k_reset<<<1, 32>>>();
    k_fused<<<NC*NB_PL, 256>>>(p_lr, I_lr, I_hr, out);
}

// round 9
// speedup vs baseline: 4.0905x; 4.0905x over previous
#include <cuda_runtime.h>

#define NC 24
#define LH 256
#define LW 256
#define PLANE (LH*LW)
#define R 8
#define EPSF 1e-4f

// scratch (allocation-free rule: __device__ globals)
__device__ float4 g_h4[NC*PLANE];   // {hsumI, hsumP, hsumIP, hsumII}
__device__ float2 g_AB[NC*PLANE];   // {A, B}

// ---------------------------------------------------------------------------
// Kernel 1: horizontal truncated window sums of I, p, I*p, I*I.
// Truncated window == full 17-tap window over a zero-padded row.
// Each thread owns 4 columns of one row; 10 independent LDG.128 per thread.
// Block = 256 threads = 4 rows x 64 col-groups. Grid = (64, NC).
// ---------------------------------------------------------------------------
__device__ __forceinline__ float4 ldz(const float* __restrict__ row, int col)
{
    if (col < 0 || col >= LW) return make_float4(0.f, 0.f, 0.f, 0.f);
    return *reinterpret_cast<const float4*>(row + col);
}

__global__ void k_hbox(const float* __restrict__ p, const float* __restrict__ I)
{
    const int tid = threadIdx.x;
    const int r   = tid >> 6;          // row in block 0..3
    const int tx  = tid & 63;
    const int row = blockIdx.x * 4 + r;
    const int pl  = blockIdx.y;
    const int gbase = pl*PLANE + row*LW;
    const int xb  = tx << 2;           // first output column

    const float* __restrict__ Irow = I + gbase;
    const float* __restrict__ Prow = p + gbase;

    // window for outputs xb..xb+3 spans columns [xb-8, xb+11]
    float4 i4[5], p4[5];
    #pragma unroll
    for (int j = 0; j < 5; j++) {
        const int col = xb - 8 + 4*j;
        i4[j] = ldz(Irow, col);
        p4[j] = ldz(Prow, col);
    }

    float iv[20], pv[20];
    #pragma unroll
    for (int j = 0; j < 5; j++) {
        iv[4*j+0] = i4[j].x; iv[4*j+1] = i4[j].y; iv[4*j+2] = i4[j].z; iv[4*j+3] = i4[j].w;
        pv[4*j+0] = p4[j].x; pv[4*j+1] = p4[j].y; pv[4*j+2] = p4[j].z; pv[4*j+3] = p4[j].w;
    }

    float sI = 0.f, sP = 0.f, sIP = 0.f, sII = 0.f;
    #pragma unroll
    for (int j = 0; j < 17; j++) {
        sI += iv[j]; sP += pv[j]; sIP += iv[j]*pv[j]; sII += iv[j]*iv[j];
    }

    float4* __restrict__ dst = g_h4 + gbase + xb;
    dst[0] = make_float4(sI, sP, sIP, sII);
    #pragma unroll
    for (int k = 1; k < 4; k++) {
        sI  += iv[16+k] - iv[k-1];
        sP  += pv[16+k] - pv[k-1];
        sIP += iv[16+k]*pv[16+k] - iv[k-1]*pv[k-1];
        sII += iv[16+k]*iv[16+k] - iv[k-1]*iv[k-1];
        dst[k] = make_float4(sI, sP, sIP, sII);
    }
}

// ---------------------------------------------------------------------------
// Kernel 2: vertical truncated sliding window + solve A,B.
// 256 threads, 1 column each; one LDG.128 per add/sub row-step.
// Chunk = 8 output rows -> 768 blocks for latency hiding. Grid = (32, NC).
// ---------------------------------------------------------------------------
__global__ void k_vbox()
{
    const int pl = blockIdx.y;
    const int c  = threadIdx.x;       // column
    const int y0 = blockIdx.x * 8;

    const float4* __restrict__ h = g_h4 + pl*PLANE + c;

    float sI = 0.f, sP = 0.f, sIP = 0.f, sII = 0.f;
    {
        const int lo = max(y0 - R, 0);
        const int hi = min(y0 + R, LH - 1);
        for (int yy = lo; yy <= hi; yy++) {
            const float4 v = h[yy*LW];
            sI += v.x; sP += v.y; sIP += v.z; sII += v.w;
        }
    }

    const float cx = (float)(min(c + R, LW-1) - max(c - R, 0) + 1);
    float2* __restrict__ ABp = g_AB + pl*PLANE + c;

    #pragma unroll
    for (int i = 0; i < 8; i++) {
        const int yo = y0 + i;
        const float cy  = (float)(min(yo + R, LH-1) - max(yo - R, 0) + 1);
        const float inv = 1.0f / (cx * cy);

        const float mI = sI*inv;
        const float mP = sP*inv;
        const float A  = (sIP*inv - mI*mP) / ((sII*inv - mI*mI) + EPSF);
        const float B  = mP - A*mI;

        ABp[yo*LW] = make_float2(A, B);

        const int ya = yo + R + 1;
        if (ya <= LH - 1) {
            const float4 v = h[ya*LW];
            sI += v.x; sP += v.y; sIP += v.z; sII += v.w;
        }
        const int ysub = yo - R;
        if (ysub >= 0) {
            const float4 v = h[ysub*LW];
            sI -= v.x; sP -= v.y; sIP -= v.z; sII -= v.w;
        }
    }
}

// ---------------------------------------------------------------------------
// Kernel 3: x4 bilinear upsample (half-pixel, edge clamp == jax linear) + apply.
// Block m covers LR rows k0=2m, 2m+1 -> HR rows 8m..8m+7 (LR rows 2m-1..2m+2).
// 256 threads; each thread -> 8x4 = 32 output px (8 independent float4 ld/st).
// Grid = (128, NC).
// ---------------------------------------------------------------------------
__global__ void k_apply(const float* __restrict__ Ihr, float* __restrict__ out)
{
    __shared__ float2 sAB[4][LW];

    const int m  = blockIdx.x;        // 0..127
    const int pl = blockIdx.y;
    const int t  = threadIdx.x;
    const int k0 = m << 1;

    const int r0 = max(k0 - 1, 0);
    const int r3 = min(k0 + 2, LH - 1);

    const float2* __restrict__ AB = g_AB + pl*PLANE;
    sAB[0][t] = AB[r0      *LW + t];
    sAB[1][t] = AB[ k0     *LW + t];
    sAB[2][t] = AB[(k0+1)  *LW + t];
    sAB[3][t] = AB[r3      *LW + t];
    __syncthreads();

    const int xm = max(t - 1, 0);
    const int xp = min(t + 1, LW - 1);

    float xA[4][4], xB[4][4];
    #pragma unroll
    for (int j = 0; j < 4; j++) {
        const float2 vm = sAB[j][xm], v0 = sAB[j][t], vp = sAB[j][xp];
        xA[j][0] = 0.375f*vm.x + 0.625f*v0.x;  xB[j][0] = 0.375f*vm.y + 0.625f*v0.y;
        xA[j][1] = 0.125f*vm.x + 0.875f*v0.x;  xB[j][1] = 0.125f*vm.y + 0.875f*v0.y;
        xA[j][2] = 0.875f*v0.x + 0.125f*vp.x;  xB[j][2] = 0.875f*v0.y + 0.125f*vp.y;
        xA[j][3] = 0.625f*v0.x + 0.375f*vp.x;  xB[j][3] = 0.625f*v0.y + 0.375f*vp.y;
    }

    const int base = ((pl << 10) + (m << 3)) * 1024 + (t << 2);

    float4 iv[8];
    #pragma unroll
    for (int i = 0; i < 8; i++)
        iv[i] = __ldcs(reinterpret_cast<const float4*>(Ihr + base + i*1024));

    // HR row 8m+i uses smem rows (J0,J1) with weights (W0,W1):
    //   i=0:(0,1,.375,.625) 1:(0,1,.125,.875) 2:(1,2,.875,.125) 3:(1,2,.625,.375)
    //   i=4:(1,2,.375,.625) 5:(1,2,.125,.875) 6:(2,3,.875,.125) 7:(2,3,.625,.375)
#define OUTV(i, W0, J0, W1, J1)                                                 \
    {                                                                           \
        float4 ov;                                                              \
        ov.x = (W0*xA[J0][0] + W1*xA[J1][0])*iv[i].x + (W0*xB[J0][0] + W1*xB[J1][0]); \
        ov.y = (W0*xA[J0][1] + W1*xA[J1][1])*iv[i].y + (W0*xB[J0][1] + W1*xB[J1][1]); \
        ov.z = (W0*xA[J0][2] + W1*xA[J1][2])*iv[i].z + (W0*xB[J0][2] + W1*xB[J1][2]); \
        ov.w = (W0*xA[J0][3] + W1*xA[J1][3])*iv[i].w + (W0*xB[J0][3] + W1*xB[J1][3]); \
        __stcs(reinterpret_cast<float4*>(out + base + (i)*1024), ov);           \
    }
    OUTV(0, 0.375f, 0, 0.625f, 1)
    OUTV(1, 0.125f, 0, 0.875f, 1)
    OUTV(2, 0.875f, 1, 0.125f, 2)
    OUTV(3, 0.625f, 1, 0.375f, 2)
    OUTV(4, 0.375f, 1, 0.625f, 2)
    OUTV(5, 0.125f, 1, 0.875f, 2)
    OUTV(6, 0.875f, 2, 0.125f, 3)
    OUTV(7, 0.625f, 2, 0.375f, 3)
#undef OUTV
}

// ---------------------------------------------------------------------------
extern "C" void kernel_launch(void* const* d_in, const int* in_sizes, int n_in,
                              void* d_out, int out_size)
{
    const float* p_lr = (const float*)d_in[0];
    const float* I_lr = (const float*)d_in[1];
    const float* I_hr = (const float*)d_in[2];
    float* out = (float*)d_out;

    k_hbox <<<dim3(LH/4, NC), 256>>>(p_lr, I_lr);
    k_vbox <<<dim3(LH/8, NC), 256>>>();
    k_apply<<<dim3(LH/2, NC), 256>>>(I_hr, out);
}